// round 15
// baseline (speedup 1.0000x reference)
#include <cuda_runtime.h>
#include <cuda_fp16.h>
#include <cstdint>

// Layer-1 precomputed per-point (fp16 G arrays), layer-2 per-pair fp16 MMA.
//   G2 = fp16(f2 @ W1[0:64,:])          (50000 x 128)
//   G1 = fp16(f1 @ W1[64:128,:] + b1)   (50000 x 128)
//   per tile: A = fp16(ELU(G2[topk] + G1[q]))  -> 128x128x128 fp16 MMA
//   out[q] = sum_k w[q,k] * ELU(A@W2 + b2)
// R14 structure; convert now uses fp16 add (__hadd2) + 2-threads-per-row
// mapping (1 topk LDG per thread, contiguous G-row halves).

namespace {
constexpr int kN1      = 50000;
constexpr int kNN      = 16;
constexpr int kQPB     = 8;                // queries per 128-row tile
constexpr int kSuper   = kN1 / (2 * kQPB); // 3125 CTA iterations (2 tiles each)
constexpr int kThreads = 512;
constexpr int kGrid    = 148;
constexpr int kNPad    = 50048;

// main kernel smem
constexpr int SM_ROWW  = 0;                    // 2 halves x 128 f32
constexpr int SM_B2    = 1024;                 // 128 f32
constexpr int SM_X     = 2048;                 // 2 halves x 32768 B (fp16 128x128)
constexpr int SM_XHSZ  = 32768;
constexpr int SM_W     = SM_X + 2 * SM_XHSZ;   // 67584
constexpr int SM_TOTAL = SM_W + 32768;         // 100352 B

// precompute kernel smem
constexpr int PP_A     = 0;
constexpr int PP_W     = 32768;
constexpr int PP_TOTAL = 65536;
}

__device__ __align__(16) unsigned char g_W2h[32768];      // W2^T fp16 swizzled
__device__ __align__(16) unsigned char g_W1h[2][32768];   // W1 halves^T fp16 (k-padded)
__device__ __align__(16) __half g_G2h[(size_t)kNPad * 128];
__device__ __align__(16) __half g_G1h[(size_t)kNPad * 128];

// [n][k] fp16 tile, 256 B per row, XOR swizzle on 16B groups
__device__ __forceinline__ uint32_t woff(int n, int k) {
    return (uint32_t)(n * 256 + ((((k >> 3) ^ (n & 7)) & 15) << 4) + (k & 7) * 2);
}

__device__ __forceinline__ uint32_t smem_u32(const void* p) {
    uint32_t a;
    asm("{ .reg .u64 t; cvta.to.shared.u64 t, %1; cvt.u32.u64 %0, t; }"
        : "=r"(a) : "l"(p));
    return a;
}
__device__ __forceinline__ void ldsm_x4(uint32_t* r, uint32_t addr) {
    asm volatile("ldmatrix.sync.aligned.m8n8.x4.shared.b16 {%0,%1,%2,%3}, [%4];"
                 : "=r"(r[0]), "=r"(r[1]), "=r"(r[2]), "=r"(r[3]) : "r"(addr));
}
__device__ __forceinline__ void mma16816(float* d, const uint32_t* a,
                                         const uint32_t* b) {
    asm volatile(
        "mma.sync.aligned.m16n8k16.row.col.f32.f16.f16.f32 "
        "{%0,%1,%2,%3}, {%4,%5,%6,%7}, {%8,%9}, {%0,%1,%2,%3};"
        : "+f"(d[0]), "+f"(d[1]), "+f"(d[2]), "+f"(d[3])
        : "r"(a[0]), "r"(a[1]), "r"(a[2]), "r"(a[3]), "r"(b[0]), "r"(b[1]));
}
__device__ __forceinline__ void barh(int id) {
    asm volatile("bar.sync %0, 256;" :: "r"(id) : "memory");
}
// packed half2 ELU: result = x>0 ? x : exp(x)-1, computed in fp16.
// ex2 argument clamped so the unselected branch stays finite (no inf*0 NaN).
__device__ __forceinline__ __half2 elu_h2v(__half2 xh) {
    __half2 xs = __hmul2(xh, __float2half2_rn(1.44269504f));
    xs = __hmin2(xs, __float2half2_rn(14.0f));
    uint32_t exu;
    asm("ex2.approx.f16x2 %0, %1;" : "=r"(exu) : "r"(*(const uint32_t*)&xs));
    const __half2 em1  = __hsub2(*(const __half2*)&exu, __float2half2_rn(1.0f));
    const __half2 mask = __hgt2(xh, __float2half2_rn(0.0f));   // 1.0 / 0.0
    return __hfma2(mask, __hsub2(xh, em1), em1);
}
__device__ __forceinline__ void split_h2(float a, float b, uint32_t& hi,
                                         uint32_t& lo) {
    const __half ah = __float2half_rn(a);
    const __half bh = __float2half_rn(b);
    __half2 h2 = __halves2half2(ah, bh);
    __half2 l2 = __halves2half2(__float2half_rn(a - __half2float(ah)),
                                __float2half_rn(b - __half2float(bh)));
    hi = *(uint32_t*)&h2;
    lo = *(uint32_t*)&l2;
}

// ---------------- W prep kernel ----------------
__global__ void prep_w_kernel(const float* __restrict__ W1,
                              const float* __restrict__ W2) {
    int idx = blockIdx.x * blockDim.x + threadIdx.x;   // 0 .. 49151
    if (idx >= 3 * 128 * 128) return;
    int sec = idx >> 14;
    int e = idx & 16383;
    int n = e >> 7;      // output channel (B row)
    int k = e & 127;     // contraction
    if (sec == 0) {
        *(__half*)(g_W2h + woff(n, k)) = __float2half_rn(W2[k * 128 + n]);
    } else {
        int p = sec - 1;                 // 0: W1 rows 0..63 (f2), 1: rows 64..127 (f1)
        float v = (k < 64) ? W1[(k + 64 * p) * 128 + n] : 0.0f;
        *(__half*)(g_W1h[p] + woff(n, k)) = __float2half_rn(v);
    }
}

// ---------------- precompute kernel: G2 / G1 (fp16 out) ----------------
__global__ void __launch_bounds__(256, 1)
precompute_kernel(const float* __restrict__ f1, const float* __restrict__ f2,
                  const float* __restrict__ b1) {
    extern __shared__ char sm[];
    const uint32_t smb = smem_u32(sm);
    const int which = blockIdx.y;             // 0 -> G2 (f2), 1 -> G1 (f1, +b1)
    const float* f = which ? f1 : f2;
    __half* G = which ? g_G1h : g_G2h;
    const int tid  = threadIdx.x;
    const int lane = tid & 31;
    const int wid  = tid >> 5;
    const int row0 = blockIdx.x * 128;

    {
        const float4* src = (const float4*)g_W1h[which];
        float4* dst = (float4*)(sm + PP_W);
        #pragma unroll
        for (int i = 0; i < 8; i++) dst[tid + i * 256] = src[tid + i * 256];
    }
    {
        #pragma unroll
        for (int it = 0; it < 4; ++it) {
            const int rr = (tid >> 3) + it * 32;
            const int g  = tid & 7;
            const int grow = min(row0 + rr, kN1 - 1);
            const float4* p = (const float4*)(f + (size_t)grow * 64) + g * 2;
            const float4 v0 = p[0], v1 = p[1];
            const float v[8] = {v0.x, v0.y, v0.z, v0.w, v1.x, v1.y, v1.z, v1.w};
            uint4 hi4, lo4;
            uint32_t* hp = (uint32_t*)&hi4;
            uint32_t* lp = (uint32_t*)&lo4;
            #pragma unroll
            for (int j = 0; j < 4; j++)
                split_h2(v[2 * j], v[2 * j + 1], hp[j], lp[j]);
            *(uint4*)(sm + PP_A + woff(rr, g * 8))      = hi4;
            *(uint4*)(sm + PP_A + woff(rr, g * 8 + 64)) = lo4;
        }
    }
    __syncthreads();

    const int wrow = (wid & 3) * 32;
    const int wcol = (wid >> 2) * 64;
    const int mat  = lane >> 3;
    const int mrow = lane & 7;

    float acc[2][8][4];
    #pragma unroll
    for (int i = 0; i < 2; i++)
        #pragma unroll
        for (int j = 0; j < 8; j++)
            #pragma unroll
            for (int e = 0; e < 4; e++) acc[i][j][e] = 0.0f;

    #pragma unroll
    for (int ks = 0; ks < 4; ++ks) {
        uint32_t bfr[4][4];
        #pragma unroll
        for (int pr = 0; pr < 4; pr++) {
            const int n  = wcol + pr * 16 + (mat >> 1) * 8 + mrow;
            const int kk = ks * 16 + (mat & 1) * 8;
            ldsm_x4(bfr[pr], smb + PP_W + woff(n, kk));
        }
        #pragma unroll
        for (int hv = 0; hv < 2; hv++) {
            uint32_t afr[2][4];
            #pragma unroll
            for (int mt = 0; mt < 2; mt++) {
                const int row = wrow + mt * 16 + (mat & 1) * 8 + mrow;
                const int kk  = ks * 16 + hv * 64 + (mat >> 1) * 8;
                ldsm_x4(afr[mt], smb + PP_A + woff(row, kk));
            }
            #pragma unroll
            for (int pr = 0; pr < 4; pr++) {
                #pragma unroll
                for (int mt = 0; mt < 2; mt++) {
                    mma16816(acc[mt][2 * pr],     afr[mt], bfr[pr]);
                    mma16816(acc[mt][2 * pr + 1], afr[mt], bfr[pr] + 2);
                }
            }
        }
    }

    #pragma unroll
    for (int mt = 0; mt < 2; mt++) {
        const int r0 = wrow + mt * 16 + (lane >> 2);
        #pragma unroll
        for (int nt = 0; nt < 8; nt++) {
            const int c = wcol + nt * 8 + (lane & 3) * 2;
            const float bb0 = which ? b1[c] : 0.0f;
            const float bb1 = which ? b1[c + 1] : 0.0f;
            const int ga = row0 + r0, gb = row0 + r0 + 8;
            if (ga < kN1)
                *(__half2*)&G[(size_t)ga * 128 + c] =
                    __floats2half2_rn(acc[mt][nt][0] + bb0, acc[mt][nt][1] + bb1);
            if (gb < kN1)
                *(__half2*)&G[(size_t)gb * 128 + c] =
                    __floats2half2_rn(acc[mt][nt][2] + bb0, acc[mt][nt][3] + bb1);
        }
    }
}

// ---------------- main persistent kernel ----------------
__global__ void __launch_bounds__(kThreads, 1)
fused_mma_kernel(const float* __restrict__ x1, const float* __restrict__ x2,
                 const void* __restrict__ topk,
                 const float* __restrict__ b2,
                 const float* __restrict__ radius, float* __restrict__ out)
{
    extern __shared__ char sm[];
    const uint32_t smb = smem_u32(sm);
    const int tid  = threadIdx.x;
    const int lane = tid & 31;
    __shared__ int s_is64;

    {
        const float4* src = (const float4*)g_W2h;
        float4* dst = (float4*)(sm + SM_W);
        #pragma unroll
        for (int i = 0; i < 4; i++) dst[tid + i * 512] = src[tid + i * 512];
    }
    if (tid < 128) ((float*)(sm + SM_B2))[tid] = b2[tid];
    if (tid < 32) {
        const int* t32 = (const int*)topk;
        unsigned m = __ballot_sync(0xFFFFFFFFu, t32[2 * tid + 1] != 0);
        if (tid == 0) s_is64 = (m == 0u) ? 1 : 0;
    }
    __syncthreads();

    const bool  is64 = (s_is64 != 0);
    const float r    = radius[0];
    const float nid  = -1.0f / (2.0f * r * r);

    const int half  = tid >> 8;            // 0: warps 0-7, 1: warps 8-15
    const int tid_h = tid & 255;
    const int hwid  = (tid >> 5) & 7;
    const int barid = 1 + half;

    const int wrow = (hwid & 3) * 32;
    const int wcol = (hwid >> 2) * 64;
    const int mat  = lane >> 3;
    const int mrow = lane & 7;

    // convert mapping: 2 threads per row, 8 contiguous 16B chunks each
    const int crr = tid_h >> 1;            // row 0..127
    const int cch = tid_h & 1;             // 128B column half
    const int cqo = crr >> 4;              // query offset within tile
    const int cnb = crr & 15;              // neighbor index

    char* xB = sm + SM_X + half * SM_XHSZ;
    const uint32_t xb = smb + SM_X + half * SM_XHSZ;
    float* roww = (float*)(sm + SM_ROWW) + half * 128;

    for (int s = blockIdx.x; s < kSuper; s += gridDim.x) {
        const int qbase = (2 * s + half) * kQPB;

        barh(barid);   // this half's prev MMA done: X safe to overwrite

        // ---- layer 1: gather fp16 G2[gi] + G1[q], hadd2+ELU -> X ----
        {
            const int q  = qbase + cqo;
            const int gi = is64 ? (int)((const long long*)topk)[q * kNN + cnb]
                                : ((const int*)topk)[q * kNN + cnb];
            const char* g2p = (const char*)g_G2h + ((size_t)gi * 256 + cch * 128);
            const char* g1p = (const char*)g_G1h + ((size_t)q * 256 + cch * 128);
            #pragma unroll
            for (int j = 0; j < 8; ++j) {
                const uint4 a = *(const uint4*)(g2p + j * 16);
                const uint4 b = *(const uint4*)(g1p + j * 16);
                uint4 h4;
                __half2* hp = (__half2*)&h4;
                #pragma unroll
                for (int e = 0; e < 4; e++) {
                    hp[e] = elu_h2v(__hadd2(((const __half2*)&a)[e],
                                            ((const __half2*)&b)[e]));
                }
                *(uint4*)(xB + woff(crr, cch * 64 + j * 8)) = h4;
            }
        }
        // ---- per-row distance weights ----
        if (tid_h < 128) {
            const int q  = qbase + (tid_h >> 4);
            const int kk = tid_h & 15;
            int gi = is64 ? (int)((const long long*)topk)[q * kNN + kk]
                          : ((const int*)topk)[q * kNN + kk];
            const float dx = x2[gi * 3 + 0] - x1[q * 3 + 0];
            const float dy = x2[gi * 3 + 1] - x1[q * 3 + 1];
            const float dz = x2[gi * 3 + 2] - x1[q * 3 + 2];
            const float w  = __expf(nid * (dx * dx + dy * dy + dz * dz));
            roww[tid_h] = (gi == 0) ? 0.0f : w;
        }
        barh(barid);

        // ---- layer 2 GEMM: 1-pass fp16 ----
        float acc[2][8][4];
        #pragma unroll
        for (int i = 0; i < 2; i++)
            #pragma unroll
            for (int j = 0; j < 8; j++)
                #pragma unroll
                for (int e = 0; e < 4; e++) acc[i][j][e] = 0.0f;

        const uint32_t wb = smb + SM_W;
        #pragma unroll 1
        for (int ks = 0; ks < 8; ++ks) {
            uint32_t bfr[4][4];
            #pragma unroll
            for (int pr = 0; pr < 4; pr++) {
                const int n  = wcol + pr * 16 + (mat >> 1) * 8 + mrow;
                const int kk = ks * 16 + (mat & 1) * 8;
                ldsm_x4(bfr[pr], wb + woff(n, kk));
            }
            uint32_t afr[2][4];
            #pragma unroll
            for (int mt = 0; mt < 2; mt++) {
                const int row = wrow + mt * 16 + (mat & 1) * 8 + mrow;
                const int kk  = ks * 16 + (mat >> 1) * 8;
                ldsm_x4(afr[mt], xb + woff(row, kk));
            }
            #pragma unroll
            for (int pr = 0; pr < 4; pr++) {
                #pragma unroll
                for (int mt = 0; mt < 2; mt++) {
                    mma16816(acc[mt][2 * pr],     afr[mt], bfr[pr]);
                    mma16816(acc[mt][2 * pr + 1], afr[mt], bfr[pr] + 2);
                }
            }
        }

        // ---- epilogue: bias + half2 ELU + weighted 16-row reduce (fp32) ----
        {
            const float* b2s = (const float*)(sm + SM_B2);
            #pragma unroll
            for (int mt = 0; mt < 2; mt++) {
                const int q  = (wrow >> 4) + mt;          // query in [0,8)
                const int r0 = wrow + mt * 16 + (lane >> 2);
                const float w0 = roww[r0], w1 = roww[r0 + 8];
                #pragma unroll
                for (int nt = 0; nt < 8; nt++) {
                    const int c  = wcol + nt * 8 + (lane & 3) * 2;
                    const float bb0 = b2s[c], bb1 = b2s[c + 1];
                    // pair rows r0 (elt 0/1) and r0+8 (elt 2/3) sharing bias cols
                    const __half2 e02 = elu_h2v(
                        __floats2half2_rn(acc[mt][nt][0] + bb0,
                                          acc[mt][nt][2] + bb0));
                    const __half2 e13 = elu_h2v(
                        __floats2half2_rn(acc[mt][nt][1] + bb1,
                                          acc[mt][nt][3] + bb1));
                    const float2 f02 = __half22float2(e02);
                    const float2 f13 = __half22float2(e13);
                    float s0 = w0 * f02.x + w1 * f02.y;
                    float s1 = w0 * f13.x + w1 * f13.y;
                    s0 += __shfl_xor_sync(0xFFFFFFFFu, s0, 4);
                    s1 += __shfl_xor_sync(0xFFFFFFFFu, s1, 4);
                    s0 += __shfl_xor_sync(0xFFFFFFFFu, s0, 8);
                    s1 += __shfl_xor_sync(0xFFFFFFFFu, s1, 8);
                    s0 += __shfl_xor_sync(0xFFFFFFFFu, s0, 16);
                    s1 += __shfl_xor_sync(0xFFFFFFFFu, s1, 16);
                    if ((lane >> 2) == 0) {
                        *(float2*)&out[(size_t)(qbase + q) * 128 + c] =
                            make_float2(s0, s1);
                    }
                }
            }
        }
    }
}

extern "C" void kernel_launch(void* const* d_in, const int* in_sizes, int n_in,
                              void* d_out, int out_size) {
    const float* f1     = (const float*)d_in[0];
    const float* f2     = (const float*)d_in[1];
    const float* x1     = (const float*)d_in[2];
    const float* x2     = (const float*)d_in[3];
    const void*  topk   = d_in[6];
    const float* W1     = (const float*)d_in[7];
    const float* b1     = (const float*)d_in[8];
    const float* W2     = (const float*)d_in[9];
    const float* b2     = (const float*)d_in[10];
    const float* radius = (const float*)d_in[11];
    float* out = (float*)d_out;

    prep_w_kernel<<<192, 256>>>(W1, W2);

    cudaFuncSetAttribute(precompute_kernel,
                         cudaFuncAttributeMaxDynamicSharedMemorySize, PP_TOTAL);
    precompute_kernel<<<dim3((kN1 + 127) / 128, 2), 256, PP_TOTAL>>>(f1, f2, b1);

    cudaFuncSetAttribute(fused_mma_kernel,
                         cudaFuncAttributeMaxDynamicSharedMemorySize, SM_TOTAL);
    fused_mma_kernel<<<kGrid, kThreads, SM_TOTAL>>>(
        x1, x2, topk, b2, radius, out);
}

// round 16
// speedup vs baseline: 1.7120x; 1.7120x over previous
#include <cuda_runtime.h>
#include <cuda_fp16.h>
#include <cstdint>

// Layer-1 precomputed per-point (fp16 G arrays), layer-2 per-pair fp16 MMA.
//   G2 = fp16(f2 @ W1[0:64,:])          (50000 x 128)
//   G1 = fp16(f1 @ W1[64:128,:] + b1)   (50000 x 128)
//   per tile: A = fp16(ELU(G2[topk] + G1[q]))  -> 128x128x128 fp16 MMA
//   out[q] = sum_k w[q,k] * ELU(A@W2 + b2)
// R14 structure + mapping (coalesced 16-threads-per-row convert);
// convert add done in fp16 (__hadd2) — the only retained R15 change.

namespace {
constexpr int kN1      = 50000;
constexpr int kNN      = 16;
constexpr int kQPB     = 8;                // queries per 128-row tile
constexpr int kSuper   = kN1 / (2 * kQPB); // 3125 CTA iterations (2 tiles each)
constexpr int kThreads = 512;
constexpr int kGrid    = 148;
constexpr int kNPad    = 50048;

// main kernel smem
constexpr int SM_ROWW  = 0;                    // 2 halves x 128 f32
constexpr int SM_B2    = 1024;                 // 128 f32
constexpr int SM_X     = 2048;                 // 2 halves x 32768 B (fp16 128x128)
constexpr int SM_XHSZ  = 32768;
constexpr int SM_W     = SM_X + 2 * SM_XHSZ;   // 67584
constexpr int SM_TOTAL = SM_W + 32768;         // 100352 B

// precompute kernel smem
constexpr int PP_A     = 0;
constexpr int PP_W     = 32768;
constexpr int PP_TOTAL = 65536;
}

__device__ __align__(16) unsigned char g_W2h[32768];      // W2^T fp16 swizzled
__device__ __align__(16) unsigned char g_W1h[2][32768];   // W1 halves^T fp16 (k-padded)
__device__ __align__(16) __half g_G2h[(size_t)kNPad * 128];
__device__ __align__(16) __half g_G1h[(size_t)kNPad * 128];

// [n][k] fp16 tile, 256 B per row, XOR swizzle on 16B groups
__device__ __forceinline__ uint32_t woff(int n, int k) {
    return (uint32_t)(n * 256 + ((((k >> 3) ^ (n & 7)) & 15) << 4) + (k & 7) * 2);
}

__device__ __forceinline__ uint32_t smem_u32(const void* p) {
    uint32_t a;
    asm("{ .reg .u64 t; cvta.to.shared.u64 t, %1; cvt.u32.u64 %0, t; }"
        : "=r"(a) : "l"(p));
    return a;
}
__device__ __forceinline__ void ldsm_x4(uint32_t* r, uint32_t addr) {
    asm volatile("ldmatrix.sync.aligned.m8n8.x4.shared.b16 {%0,%1,%2,%3}, [%4];"
                 : "=r"(r[0]), "=r"(r[1]), "=r"(r[2]), "=r"(r[3]) : "r"(addr));
}
__device__ __forceinline__ void mma16816(float* d, const uint32_t* a,
                                         const uint32_t* b) {
    asm volatile(
        "mma.sync.aligned.m16n8k16.row.col.f32.f16.f16.f32 "
        "{%0,%1,%2,%3}, {%4,%5,%6,%7}, {%8,%9}, {%0,%1,%2,%3};"
        : "+f"(d[0]), "+f"(d[1]), "+f"(d[2]), "+f"(d[3])
        : "r"(a[0]), "r"(a[1]), "r"(a[2]), "r"(a[3]), "r"(b[0]), "r"(b[1]));
}
__device__ __forceinline__ void barh(int id) {
    asm volatile("bar.sync %0, 256;" :: "r"(id) : "memory");
}
// packed half2 ELU: result = x>0 ? x : exp(x)-1, computed in fp16.
// ex2 argument clamped so the unselected branch stays finite (no inf*0 NaN).
__device__ __forceinline__ __half2 elu_h2v(__half2 xh) {
    __half2 xs = __hmul2(xh, __float2half2_rn(1.44269504f));
    xs = __hmin2(xs, __float2half2_rn(14.0f));
    uint32_t exu;
    asm("ex2.approx.f16x2 %0, %1;" : "=r"(exu) : "r"(*(const uint32_t*)&xs));
    const __half2 em1  = __hsub2(*(const __half2*)&exu, __float2half2_rn(1.0f));
    const __half2 mask = __hgt2(xh, __float2half2_rn(0.0f));   // 1.0 / 0.0
    return __hfma2(mask, __hsub2(xh, em1), em1);
}
__device__ __forceinline__ void split_h2(float a, float b, uint32_t& hi,
                                         uint32_t& lo) {
    const __half ah = __float2half_rn(a);
    const __half bh = __float2half_rn(b);
    __half2 h2 = __halves2half2(ah, bh);
    __half2 l2 = __halves2half2(__float2half_rn(a - __half2float(ah)),
                                __float2half_rn(b - __half2float(bh)));
    hi = *(uint32_t*)&h2;
    lo = *(uint32_t*)&l2;
}

// ---------------- W prep kernel ----------------
__global__ void prep_w_kernel(const float* __restrict__ W1,
                              const float* __restrict__ W2) {
    int idx = blockIdx.x * blockDim.x + threadIdx.x;   // 0 .. 49151
    if (idx >= 3 * 128 * 128) return;
    int sec = idx >> 14;
    int e = idx & 16383;
    int n = e >> 7;      // output channel (B row)
    int k = e & 127;     // contraction
    if (sec == 0) {
        *(__half*)(g_W2h + woff(n, k)) = __float2half_rn(W2[k * 128 + n]);
    } else {
        int p = sec - 1;                 // 0: W1 rows 0..63 (f2), 1: rows 64..127 (f1)
        float v = (k < 64) ? W1[(k + 64 * p) * 128 + n] : 0.0f;
        *(__half*)(g_W1h[p] + woff(n, k)) = __float2half_rn(v);
    }
}

// ---------------- precompute kernel: G2 / G1 (fp16 out) ----------------
__global__ void __launch_bounds__(256, 1)
precompute_kernel(const float* __restrict__ f1, const float* __restrict__ f2,
                  const float* __restrict__ b1) {
    extern __shared__ char sm[];
    const uint32_t smb = smem_u32(sm);
    const int which = blockIdx.y;             // 0 -> G2 (f2), 1 -> G1 (f1, +b1)
    const float* f = which ? f1 : f2;
    __half* G = which ? g_G1h : g_G2h;
    const int tid  = threadIdx.x;
    const int lane = tid & 31;
    const int wid  = tid >> 5;
    const int row0 = blockIdx.x * 128;

    {
        const float4* src = (const float4*)g_W1h[which];
        float4* dst = (float4*)(sm + PP_W);
        #pragma unroll
        for (int i = 0; i < 8; i++) dst[tid + i * 256] = src[tid + i * 256];
    }
    {
        #pragma unroll
        for (int it = 0; it < 4; ++it) {
            const int rr = (tid >> 3) + it * 32;
            const int g  = tid & 7;
            const int grow = min(row0 + rr, kN1 - 1);
            const float4* p = (const float4*)(f + (size_t)grow * 64) + g * 2;
            const float4 v0 = p[0], v1 = p[1];
            const float v[8] = {v0.x, v0.y, v0.z, v0.w, v1.x, v1.y, v1.z, v1.w};
            uint4 hi4, lo4;
            uint32_t* hp = (uint32_t*)&hi4;
            uint32_t* lp = (uint32_t*)&lo4;
            #pragma unroll
            for (int j = 0; j < 4; j++)
                split_h2(v[2 * j], v[2 * j + 1], hp[j], lp[j]);
            *(uint4*)(sm + PP_A + woff(rr, g * 8))      = hi4;
            *(uint4*)(sm + PP_A + woff(rr, g * 8 + 64)) = lo4;
        }
    }
    __syncthreads();

    const int wrow = (wid & 3) * 32;
    const int wcol = (wid >> 2) * 64;
    const int mat  = lane >> 3;
    const int mrow = lane & 7;

    float acc[2][8][4];
    #pragma unroll
    for (int i = 0; i < 2; i++)
        #pragma unroll
        for (int j = 0; j < 8; j++)
            #pragma unroll
            for (int e = 0; e < 4; e++) acc[i][j][e] = 0.0f;

    #pragma unroll
    for (int ks = 0; ks < 4; ++ks) {
        uint32_t bfr[4][4];
        #pragma unroll
        for (int pr = 0; pr < 4; pr++) {
            const int n  = wcol + pr * 16 + (mat >> 1) * 8 + mrow;
            const int kk = ks * 16 + (mat & 1) * 8;
            ldsm_x4(bfr[pr], smb + PP_W + woff(n, kk));
        }
        #pragma unroll
        for (int hv = 0; hv < 2; hv++) {
            uint32_t afr[2][4];
            #pragma unroll
            for (int mt = 0; mt < 2; mt++) {
                const int row = wrow + mt * 16 + (mat & 1) * 8 + mrow;
                const int kk  = ks * 16 + hv * 64 + (mat >> 1) * 8;
                ldsm_x4(afr[mt], smb + PP_A + woff(row, kk));
            }
            #pragma unroll
            for (int pr = 0; pr < 4; pr++) {
                #pragma unroll
                for (int mt = 0; mt < 2; mt++) {
                    mma16816(acc[mt][2 * pr],     afr[mt], bfr[pr]);
                    mma16816(acc[mt][2 * pr + 1], afr[mt], bfr[pr] + 2);
                }
            }
        }
    }

    #pragma unroll
    for (int mt = 0; mt < 2; mt++) {
        const int r0 = wrow + mt * 16 + (lane >> 2);
        #pragma unroll
        for (int nt = 0; nt < 8; nt++) {
            const int c = wcol + nt * 8 + (lane & 3) * 2;
            const float bb0 = which ? b1[c] : 0.0f;
            const float bb1 = which ? b1[c + 1] : 0.0f;
            const int ga = row0 + r0, gb = row0 + r0 + 8;
            if (ga < kN1)
                *(__half2*)&G[(size_t)ga * 128 + c] =
                    __floats2half2_rn(acc[mt][nt][0] + bb0, acc[mt][nt][1] + bb1);
            if (gb < kN1)
                *(__half2*)&G[(size_t)gb * 128 + c] =
                    __floats2half2_rn(acc[mt][nt][2] + bb0, acc[mt][nt][3] + bb1);
        }
    }
}

// ---------------- main persistent kernel ----------------
__global__ void __launch_bounds__(kThreads, 1)
fused_mma_kernel(const float* __restrict__ x1, const float* __restrict__ x2,
                 const void* __restrict__ topk,
                 const float* __restrict__ b2,
                 const float* __restrict__ radius, float* __restrict__ out)
{
    extern __shared__ char sm[];
    const uint32_t smb = smem_u32(sm);
    const int tid  = threadIdx.x;
    const int lane = tid & 31;
    __shared__ int s_is64;

    {
        const float4* src = (const float4*)g_W2h;
        float4* dst = (float4*)(sm + SM_W);
        #pragma unroll
        for (int i = 0; i < 4; i++) dst[tid + i * 512] = src[tid + i * 512];
    }
    if (tid < 128) ((float*)(sm + SM_B2))[tid] = b2[tid];
    if (tid < 32) {
        const int* t32 = (const int*)topk;
        unsigned m = __ballot_sync(0xFFFFFFFFu, t32[2 * tid + 1] != 0);
        if (tid == 0) s_is64 = (m == 0u) ? 1 : 0;
    }
    __syncthreads();

    const bool  is64 = (s_is64 != 0);
    const float r    = radius[0];
    const float nid  = -1.0f / (2.0f * r * r);

    const int half  = tid >> 8;            // 0: warps 0-7, 1: warps 8-15
    const int tid_h = tid & 255;
    const int hwid  = (tid >> 5) & 7;
    const int barid = 1 + half;

    const int wrow = (hwid & 3) * 32;
    const int wcol = (hwid >> 2) * 64;
    const int mat  = lane >> 3;
    const int mrow = lane & 7;

    char* xB = sm + SM_X + half * SM_XHSZ;
    const uint32_t xb = smb + SM_X + half * SM_XHSZ;
    float* roww = (float*)(sm + SM_ROWW) + half * 128;

    for (int s = blockIdx.x; s < kSuper; s += gridDim.x) {
        const int qbase = (2 * s + half) * kQPB;

        barh(barid);   // this half's prev MMA done: X safe to overwrite

        // ---- layer 1: gather fp16 G2[gi] + G1[q], hadd2+ELU -> X ----
        // (R14 coalesced mapping: 16 threads span one row's 16 x 16B chunks)
        {
            const int g = tid_h & 15;      // 16B group (8 halves) per row
            #pragma unroll
            for (int it = 0; it < 8; ++it) {
                const int rr = (tid_h >> 4) + it * 16;   // row 0..127
                const int q  = qbase + (rr >> 4);
                const int nb = rr & 15;
                const int gi = is64 ? (int)((const long long*)topk)[q * kNN + nb]
                                    : ((const int*)topk)[q * kNN + nb];
                const uint4 a = *(const uint4*)((const char*)g_G2h
                                 + ((size_t)gi * 256 + g * 16));
                const uint4 b = *(const uint4*)((const char*)g_G1h
                                 + ((size_t)q * 256 + g * 16));
                uint4 h4;
                __half2* hp = (__half2*)&h4;
                #pragma unroll
                for (int j = 0; j < 4; j++) {
                    hp[j] = elu_h2v(__hadd2(((const __half2*)&a)[j],
                                            ((const __half2*)&b)[j]));
                }
                *(uint4*)(xB + woff(rr, g * 8)) = h4;
            }
        }
        // ---- per-row distance weights ----
        if (tid_h < 128) {
            const int q  = qbase + (tid_h >> 4);
            const int kk = tid_h & 15;
            int gi = is64 ? (int)((const long long*)topk)[q * kNN + kk]
                          : ((const int*)topk)[q * kNN + kk];
            const float dx = x2[gi * 3 + 0] - x1[q * 3 + 0];
            const float dy = x2[gi * 3 + 1] - x1[q * 3 + 1];
            const float dz = x2[gi * 3 + 2] - x1[q * 3 + 2];
            const float w  = __expf(nid * (dx * dx + dy * dy + dz * dz));
            roww[tid_h] = (gi == 0) ? 0.0f : w;
        }
        barh(barid);

        // ---- layer 2 GEMM: 1-pass fp16 ----
        float acc[2][8][4];
        #pragma unroll
        for (int i = 0; i < 2; i++)
            #pragma unroll
            for (int j = 0; j < 8; j++)
                #pragma unroll
                for (int e = 0; e < 4; e++) acc[i][j][e] = 0.0f;

        const uint32_t wb = smb + SM_W;
        #pragma unroll 1
        for (int ks = 0; ks < 8; ++ks) {
            uint32_t bfr[4][4];
            #pragma unroll
            for (int pr = 0; pr < 4; pr++) {
                const int n  = wcol + pr * 16 + (mat >> 1) * 8 + mrow;
                const int kk = ks * 16 + (mat & 1) * 8;
                ldsm_x4(bfr[pr], wb + woff(n, kk));
            }
            uint32_t afr[2][4];
            #pragma unroll
            for (int mt = 0; mt < 2; mt++) {
                const int row = wrow + mt * 16 + (mat & 1) * 8 + mrow;
                const int kk  = ks * 16 + (mat >> 1) * 8;
                ldsm_x4(afr[mt], xb + woff(row, kk));
            }
            #pragma unroll
            for (int pr = 0; pr < 4; pr++) {
                #pragma unroll
                for (int mt = 0; mt < 2; mt++) {
                    mma16816(acc[mt][2 * pr],     afr[mt], bfr[pr]);
                    mma16816(acc[mt][2 * pr + 1], afr[mt], bfr[pr] + 2);
                }
            }
        }

        // ---- epilogue: bias + half2 ELU + weighted 16-row reduce (fp32) ----
        {
            const float* b2s = (const float*)(sm + SM_B2);
            #pragma unroll
            for (int mt = 0; mt < 2; mt++) {
                const int q  = (wrow >> 4) + mt;          // query in [0,8)
                const int r0 = wrow + mt * 16 + (lane >> 2);
                const float w0 = roww[r0], w1 = roww[r0 + 8];
                #pragma unroll
                for (int nt = 0; nt < 8; nt++) {
                    const int c  = wcol + nt * 8 + (lane & 3) * 2;
                    const float bb0 = b2s[c], bb1 = b2s[c + 1];
                    // pair rows r0 (elt 0/1) and r0+8 (elt 2/3) sharing bias cols
                    const __half2 e02 = elu_h2v(
                        __floats2half2_rn(acc[mt][nt][0] + bb0,
                                          acc[mt][nt][2] + bb0));
                    const __half2 e13 = elu_h2v(
                        __floats2half2_rn(acc[mt][nt][1] + bb1,
                                          acc[mt][nt][3] + bb1));
                    const float2 f02 = __half22float2(e02);
                    const float2 f13 = __half22float2(e13);
                    float s0 = w0 * f02.x + w1 * f02.y;
                    float s1 = w0 * f13.x + w1 * f13.y;
                    s0 += __shfl_xor_sync(0xFFFFFFFFu, s0, 4);
                    s1 += __shfl_xor_sync(0xFFFFFFFFu, s1, 4);
                    s0 += __shfl_xor_sync(0xFFFFFFFFu, s0, 8);
                    s1 += __shfl_xor_sync(0xFFFFFFFFu, s1, 8);
                    s0 += __shfl_xor_sync(0xFFFFFFFFu, s0, 16);
                    s1 += __shfl_xor_sync(0xFFFFFFFFu, s1, 16);
                    if ((lane >> 2) == 0) {
                        *(float2*)&out[(size_t)(qbase + q) * 128 + c] =
                            make_float2(s0, s1);
                    }
                }
            }
        }
    }
}

extern "C" void kernel_launch(void* const* d_in, const int* in_sizes, int n_in,
                              void* d_out, int out_size) {
    const float* f1     = (const float*)d_in[0];
    const float* f2     = (const float*)d_in[1];
    const float* x1     = (const float*)d_in[2];
    const float* x2     = (const float*)d_in[3];
    const void*  topk   = d_in[6];
    const float* W1     = (const float*)d_in[7];
    const float* b1     = (const float*)d_in[8];
    const float* W2     = (const float*)d_in[9];
    const float* b2     = (const float*)d_in[10];
    const float* radius = (const float*)d_in[11];
    float* out = (float*)d_out;

    prep_w_kernel<<<192, 256>>>(W1, W2);

    cudaFuncSetAttribute(precompute_kernel,
                         cudaFuncAttributeMaxDynamicSharedMemorySize, PP_TOTAL);
    precompute_kernel<<<dim3((kN1 + 127) / 128, 2), 256, PP_TOTAL>>>(f1, f2, b1);

    cudaFuncSetAttribute(fused_mma_kernel,
                         cudaFuncAttributeMaxDynamicSharedMemorySize, SM_TOTAL);
    fused_mma_kernel<<<kGrid, kThreads, SM_TOTAL>>>(
        x1, x2, topk, b2, radius, out);
}